// round 5
// baseline (speedup 1.0000x reference)
#include <cuda_runtime.h>

#define D     64
#define EPSV  0.1f
#define MAXN  225000
#define MAXE  3200000

// Scratch (no allocations allowed). Zero-initialized at module load.
// INVARIANT: g_deg is all-zero on entry to kernel_launch; the last gather
// kernel re-zeroes it, so the invariant holds across calls/replays.
__device__ float        g_xA[MAXN * D];
__device__ float        g_xB[MAXN * D];
__device__ unsigned int g_deg[MAXN];
__device__ int          g_rowptr[MAXN + 1];
__device__ int          g_cursor[MAXN];
__device__ int2         g_cw[MAXE];     // {src_col, weight_bits}

// ---------------------------------------------------------------------------
__global__ void deg_kernel(const int* __restrict__ dst, int E) {
    int e = blockIdx.x * blockDim.x + threadIdx.x;
    if (e < E) atomicAdd(&g_deg[dst[e]], 1u);
}

// ---------------------------------------------------------------------------
// Single-block exclusive scan of g_deg -> g_rowptr / g_cursor.
// ---------------------------------------------------------------------------
__global__ void scan_all(int N) {
    __shared__ unsigned sums[1024];
    int tid = threadIdx.x;
    int chunk = (N + 1023) >> 10;
    int beg = tid * chunk;
    int end = min(beg + chunk, N);
    if (end < beg) end = beg;

    unsigned s = 0;
    for (int i = beg; i < end; i++) s += g_deg[i];
    sums[tid] = s;
    __syncthreads();
    for (int off = 1; off < 1024; off <<= 1) {
        unsigned t = (tid >= off) ? sums[tid - off] : 0u;
        __syncthreads();
        sums[tid] += t;
        __syncthreads();
    }
    unsigned run = sums[tid] - s;     // exclusive prefix of this chunk
    for (int i = beg; i < end; i++) {
        g_rowptr[i] = (int)run;
        g_cursor[i] = (int)run;
        run += g_deg[i];
    }
    if (tid == 1023) g_rowptr[N] = (int)run;  // == E
}

// ---------------------------------------------------------------------------
// fill CSR: w = 1/sqrt(deg[s]*deg[d])  (edge endpoints always have deg >= 1)
// ---------------------------------------------------------------------------
__global__ void fill_kernel(const int* __restrict__ src,
                            const int* __restrict__ dst, int E) {
    int e = blockIdx.x * blockDim.x + threadIdx.x;
    if (e >= E) return;
    int s = __ldg(src + e);
    int d = __ldg(dst + e);
    int pos = atomicAdd(&g_cursor[d], 1);
    float w = rsqrtf((float)(__ldg(g_deg + s) * __ldg(g_deg + d)));
    g_cw[pos] = make_int2(s, __float_as_int(w));
}

// ---------------------------------------------------------------------------
// Fused gather SpMM + noise perturbation + output accumulation.
// Warp per node; lane holds float2 of the 64-wide row. Uniform trip count
// within a warp -> no divergence. Templated per layer:
//   LAYER 0: read Gu/Gi directly, write g_xB, acc  = s/3
//   LAYER 1: read g_xB,           write g_xA, acc += s/3
//   LAYER 2: read g_xA,           no x write, acc += s/3, re-zero g_deg
// ---------------------------------------------------------------------------
__device__ __forceinline__ float sgnf(float v) {
    return (v > 0.f) ? 1.f : ((v < 0.f) ? -1.f : 0.f);
}

template <int LAYER>
__global__ void gather_perturb(const float* __restrict__ Gu,
                               const float* __restrict__ Gi,
                               const float* __restrict__ noise,
                               float* __restrict__ acc,
                               int U, int N) {
    long long t = (long long)blockIdx.x * blockDim.x + threadIdx.x;
    int n = (int)(t >> 5);
    if (n >= N) return;
    int lane = threadIdx.x & 31;

    const float* x = (LAYER == 1) ? g_xB : g_xA;   // LAYER 2 reads g_xA

    int beg = __ldg(g_rowptr + n);
    int end = __ldg(g_rowptr + n + 1);

    float2 s = make_float2(0.f, 0.f);
    for (int j0 = beg; j0 < end; j0 += 32) {
        int jj = j0 + lane;
        int2 cw = (jj < end) ? __ldg(g_cw + jj) : make_int2(0, 0);
        int cnt = min(32, end - j0);
        for (int k = 0; k < cnt; k++) {
            int   cc = __shfl_sync(0xFFFFFFFFu, cw.x, k);
            float ww = __int_as_float(__shfl_sync(0xFFFFFFFFu, cw.y, k));
            const float2* rp;
            if (LAYER == 0)
                rp = (cc < U) ? (const float2*)(Gu + (long long)cc * D)
                              : (const float2*)(Gi + (long long)(cc - U) * D);
            else
                rp = (const float2*)(x + (long long)cc * D);
            float2 v = __ldg(rp + lane);
            s.x += v.x * ww;
            s.y += v.y * ww;
        }
    }

    // perturb: s += sign(s) * (noise_row / max(||noise_row||,1e-12)) * EPS
    float2 nv = __ldg((const float2*)(noise + (long long)n * D) + lane);
    float ss = nv.x * nv.x + nv.y * nv.y;
    #pragma unroll
    for (int o = 16; o; o >>= 1) ss += __shfl_xor_sync(0xFFFFFFFFu, ss, o);
    float scale = EPSV / fmaxf(sqrtf(ss), 1e-12f);
    s.x += sgnf(s.x) * nv.x * scale;
    s.y += sgnf(s.y) * nv.y * scale;

    if (LAYER == 0)
        ((float2*)(g_xB + (long long)n * D))[lane] = s;
    else if (LAYER == 1)
        ((float2*)(g_xA + (long long)n * D))[lane] = s;

    const float third = 1.f / 3.f;
    float2* ap = (float2*)(acc + (long long)n * D) + lane;
    if (LAYER == 0) {
        *ap = make_float2(s.x * third, s.y * third);
    } else {
        float2 av = *ap;
        av.x += s.x * third;
        av.y += s.y * third;
        *ap = av;
    }

    if (LAYER == 2 && lane == 0) g_deg[n] = 0u;   // restore invariant
}

// ---------------------------------------------------------------------------
extern "C" void kernel_launch(void* const* d_in, const int* in_sizes, int n_in,
                              void* d_out, int out_size) {
    const float* Gu = (const float*)d_in[0];
    const float* Gi = (const float*)d_in[1];
    const float* nz = (const float*)d_in[2];
    const int*   ei = (const int*)d_in[3];

    int U = in_sizes[0] / D;
    int I = in_sizes[1] / D;
    int N = U + I;
    int E = in_sizes[3] / 2;

    const int* src = ei;
    const int* dst = ei + E;
    float* acc = (float*)d_out;

    const int TPB = 256;
    int blks_E = (E + TPB - 1) / TPB;
    long long node_threads = (long long)N * 32;
    int blks_g = (int)((node_threads + TPB - 1) / TPB);

    long long nd = (long long)N * D;

    deg_kernel<<<blks_E, TPB>>>(dst, E);          // launch 0
    scan_all<<<1, 1024>>>(N);                     // launch 1
    fill_kernel<<<blks_E, TPB>>>(src, dst, E);    // launch 2
    gather_perturb<0><<<blks_g, TPB>>>(Gu, Gi, nz,          acc, U, N); // 3 (profiled)
    gather_perturb<1><<<blks_g, TPB>>>(Gu, Gi, nz + nd,     acc, U, N); // 4
    gather_perturb<2><<<blks_g, TPB>>>(Gu, Gi, nz + 2 * nd, acc, U, N); // 5
}

// round 6
// speedup vs baseline: 1.3828x; 1.3828x over previous
#include <cuda_runtime.h>

#define D     64
#define EPSV  0.1f
#define MAXN  225000
#define MAXE  3200000
#define NBLK  512

// Scratch (no allocations allowed). Zero-initialized at module load.
// INVARIANT: g_deg is all-zero on entry to kernel_launch; gather<2>
// re-zeroes it, so the invariant holds across calls/graph replays.
__device__ float        g_xA[MAXN * D];
__device__ float        g_xB[MAXN * D];
__device__ float        g_dinv[MAXN];
__device__ unsigned int g_deg[MAXN];
__device__ unsigned int g_bsum[NBLK];
__device__ unsigned int g_boff[NBLK];
__device__ int          g_rowptr[MAXN + 1];
__device__ int          g_cursor[MAXN];
__device__ int2         g_cw[MAXE];     // {src_col, weight_bits}

// ---------------------------------------------------------------------------
__global__ void deg_kernel(const int* __restrict__ dst, int E) {
    int e = blockIdx.x * blockDim.x + threadIdx.x;
    if (e < E) atomicAdd(&g_deg[dst[e]], 1u);
}

__global__ void dinv_kernel(int N) {
    int n = blockIdx.x * blockDim.x + threadIdx.x;
    if (n < N) {
        unsigned int d = g_deg[n];
        g_dinv[n] = d ? rsqrtf((float)d) : 0.f;
    }
}

// ---------------------------------------------------------------------------
// Coalesced 3-kernel exclusive scan of g_deg -> g_rowptr/g_cursor (tiles of 1024).
// ---------------------------------------------------------------------------
__global__ void tile_reduce(int N) {
    int i = blockIdx.x * 1024 + threadIdx.x;
    int lane = threadIdx.x & 31, wid = threadIdx.x >> 5;
    unsigned v = (i < N) ? g_deg[i] : 0u;
    #pragma unroll
    for (int o = 16; o; o >>= 1) v += __shfl_down_sync(0xFFFFFFFFu, v, o);
    __shared__ unsigned ws[32];
    if (lane == 0) ws[wid] = v;
    __syncthreads();
    if (wid == 0) {
        v = ws[lane];
        #pragma unroll
        for (int o = 16; o; o >>= 1) v += __shfl_down_sync(0xFFFFFFFFu, v, o);
        if (lane == 0) g_bsum[blockIdx.x] = v;
    }
}

__global__ void scan_bsums(int B) {           // single block, 1024 threads
    __shared__ unsigned sh[1024];
    int tid = threadIdx.x;
    unsigned v = (tid < B) ? g_bsum[tid] : 0u;
    sh[tid] = v;
    __syncthreads();
    for (int off = 1; off < 1024; off <<= 1) {
        unsigned t = (tid >= off) ? sh[tid - off] : 0u;
        __syncthreads();
        sh[tid] += t;
        __syncthreads();
    }
    if (tid < B) g_boff[tid] = sh[tid] - v;   // exclusive
}

__global__ void emit_rowptr(int N) {
    int b = blockIdx.x, tid = threadIdx.x;
    int lane = tid & 31, wid = tid >> 5;
    int i = b * 1024 + tid;
    unsigned v = (i < N) ? g_deg[i] : 0u;
    unsigned x = v;
    #pragma unroll
    for (int o = 1; o < 32; o <<= 1) {
        unsigned t = __shfl_up_sync(0xFFFFFFFFu, x, o);
        if (lane >= o) x += t;
    }
    __shared__ unsigned wsum[32];
    if (lane == 31) wsum[wid] = x;
    __syncthreads();
    if (wid == 0) {
        unsigned w = wsum[lane], orig = w;
        #pragma unroll
        for (int o = 1; o < 32; o <<= 1) {
            unsigned t = __shfl_up_sync(0xFFFFFFFFu, w, o);
            if (lane >= o) w += t;
        }
        wsum[lane] = w - orig;
    }
    __syncthreads();
    unsigned ex = (x - v) + wsum[wid] + g_boff[b];
    if (i < N) {
        g_rowptr[i] = (int)ex;
        g_cursor[i] = (int)ex;
        if (i == N - 1) g_rowptr[N] = (int)(ex + v);
    }
}

// ---------------------------------------------------------------------------
__global__ void fill_kernel(const int* __restrict__ src,
                            const int* __restrict__ dst, int E) {
    int e = blockIdx.x * blockDim.x + threadIdx.x;
    if (e >= E) return;
    int s = __ldg(src + e);
    int d = __ldg(dst + e);
    int pos = atomicAdd(&g_cursor[d], 1);
    float w = __ldg(g_dinv + s) * __ldg(g_dinv + d);
    g_cw[pos] = make_int2(s, __float_as_int(w));
}

// ---------------------------------------------------------------------------
// Fused gather SpMM + noise perturbation + output accumulation.
// Warp per node; lane holds float2. Inner loop fully unrolled with warp-
// uniform predication so up to cnt independent LDGs are in flight per lane.
//   LAYER 0: read Gu/Gi directly, write g_xB, acc  = s/3
//   LAYER 1: read g_xB,           write g_xA, acc += s/3
//   LAYER 2: read g_xA,           no x write, acc += s/3, re-zero g_deg
// ---------------------------------------------------------------------------
__device__ __forceinline__ float sgnf(float v) {
    return (v > 0.f) ? 1.f : ((v < 0.f) ? -1.f : 0.f);
}

template <int LAYER>
__global__ void gather_perturb(const float* __restrict__ Gu,
                               const float* __restrict__ Gi,
                               const float* __restrict__ noise,
                               float* __restrict__ acc,
                               int U, int N) {
    long long t = (long long)blockIdx.x * blockDim.x + threadIdx.x;
    int n = (int)(t >> 5);
    if (n >= N) return;
    int lane = threadIdx.x & 31;

    const float* x = (LAYER == 1) ? g_xB : g_xA;   // LAYER 2 reads g_xA

    int beg = __ldg(g_rowptr + n);
    int end = __ldg(g_rowptr + n + 1);

    float2 s = make_float2(0.f, 0.f);
    for (int j0 = beg; j0 < end; j0 += 32) {
        int jj = j0 + lane;
        int2 cw = (jj < end) ? __ldg(g_cw + jj) : make_int2(0, 0);
        int cnt = min(32, end - j0);     // warp-uniform
        #pragma unroll
        for (int k = 0; k < 32; k++) {
            if (k < cnt) {
                int   cc = __shfl_sync(0xFFFFFFFFu, cw.x, k);
                float ww = __int_as_float(__shfl_sync(0xFFFFFFFFu, cw.y, k));
                const float2* rp;
                if (LAYER == 0)
                    rp = (cc < U) ? (const float2*)(Gu + (long long)cc * D)
                                  : (const float2*)(Gi + (long long)(cc - U) * D);
                else
                    rp = (const float2*)(x + (long long)cc * D);
                float2 v = __ldg(rp + lane);
                s.x += v.x * ww;
                s.y += v.y * ww;
            }
        }
    }

    // perturb: s += sign(s) * (noise_row / max(||noise_row||,1e-12)) * EPS
    float2 nv = __ldg((const float2*)(noise + (long long)n * D) + lane);
    float ss = nv.x * nv.x + nv.y * nv.y;
    #pragma unroll
    for (int o = 16; o; o >>= 1) ss += __shfl_xor_sync(0xFFFFFFFFu, ss, o);
    float scale = EPSV / fmaxf(sqrtf(ss), 1e-12f);
    s.x += sgnf(s.x) * nv.x * scale;
    s.y += sgnf(s.y) * nv.y * scale;

    if (LAYER == 0)
        ((float2*)(g_xB + (long long)n * D))[lane] = s;
    else if (LAYER == 1)
        ((float2*)(g_xA + (long long)n * D))[lane] = s;

    const float third = 1.f / 3.f;
    float2* ap = (float2*)(acc + (long long)n * D) + lane;
    if (LAYER == 0) {
        *ap = make_float2(s.x * third, s.y * third);
    } else {
        float2 av = *ap;
        av.x += s.x * third;
        av.y += s.y * third;
        *ap = av;
    }

    if (LAYER == 2 && lane == 0) g_deg[n] = 0u;   // restore invariant
}

// ---------------------------------------------------------------------------
extern "C" void kernel_launch(void* const* d_in, const int* in_sizes, int n_in,
                              void* d_out, int out_size) {
    const float* Gu = (const float*)d_in[0];
    const float* Gi = (const float*)d_in[1];
    const float* nz = (const float*)d_in[2];
    const int*   ei = (const int*)d_in[3];

    int U = in_sizes[0] / D;
    int I = in_sizes[1] / D;
    int N = U + I;
    int E = in_sizes[3] / 2;

    const int* src = ei;
    const int* dst = ei + E;
    float* acc = (float*)d_out;

    const int TPB = 256;
    int blks_E = (E + TPB - 1) / TPB;
    int blks_N = (N + TPB - 1) / TPB;
    int B      = (N + 1023) / 1024;
    long long node_threads = (long long)N * 32;
    int blks_g = (int)((node_threads + TPB - 1) / TPB);

    long long nd = (long long)N * D;

    deg_kernel<<<blks_E, TPB>>>(dst, E);
    dinv_kernel<<<blks_N, TPB>>>(N);
    tile_reduce<<<B, 1024>>>(N);
    scan_bsums<<<1, 1024>>>(B);
    emit_rowptr<<<B, 1024>>>(N);
    fill_kernel<<<blks_E, TPB>>>(src, dst, E);
    gather_perturb<0><<<blks_g, TPB>>>(Gu, Gi, nz,          acc, U, N);
    gather_perturb<1><<<blks_g, TPB>>>(Gu, Gi, nz + nd,     acc, U, N);
    gather_perturb<2><<<blks_g, TPB>>>(Gu, Gi, nz + 2 * nd, acc, U, N);
}

// round 7
// speedup vs baseline: 2.1042x; 1.5217x over previous
#include <cuda_runtime.h>

#define D     64
#define EPSV  0.1f
#define MAXN  225000
#define MAXE  3200000
#define NBLK  512

// Scratch (no allocations allowed). Zero-initialized at module load.
// INVARIANT: g_deg is all-zero on entry to kernel_launch; gather<2>
// re-zeroes it, so the invariant holds across calls/graph replays.
__device__ float        g_xA[MAXN * D];   // prescaled layer input (dinv * x)
__device__ float        g_xB[MAXN * D];
__device__ float        g_dinv[MAXN];
__device__ unsigned int g_deg[MAXN];
__device__ unsigned int g_bsum[NBLK];
__device__ unsigned int g_boff[NBLK];
__device__ int          g_rowptr[MAXN + 1];
__device__ int          g_cursor[MAXN];
__device__ int          g_col[MAXE];      // CSR columns (src node per edge)

// ---------------------------------------------------------------------------
__global__ void deg_kernel(const int* __restrict__ dst, int E) {
    int e = blockIdx.x * blockDim.x + threadIdx.x;
    if (e < E) atomicAdd(&g_deg[dst[e]], 1u);
}

__global__ void dinv_kernel(int N) {
    int n = blockIdx.x * blockDim.x + threadIdx.x;
    if (n < N) {
        unsigned int d = g_deg[n];
        g_dinv[n] = d ? rsqrtf((float)d) : 0.f;
    }
}

// ---------------------------------------------------------------------------
// Coalesced 3-kernel exclusive scan of g_deg -> g_rowptr/g_cursor.
// ---------------------------------------------------------------------------
__global__ void tile_reduce(int N) {
    int i = blockIdx.x * 1024 + threadIdx.x;
    int lane = threadIdx.x & 31, wid = threadIdx.x >> 5;
    unsigned v = (i < N) ? g_deg[i] : 0u;
    #pragma unroll
    for (int o = 16; o; o >>= 1) v += __shfl_down_sync(0xFFFFFFFFu, v, o);
    __shared__ unsigned ws[32];
    if (lane == 0) ws[wid] = v;
    __syncthreads();
    if (wid == 0) {
        v = ws[lane];
        #pragma unroll
        for (int o = 16; o; o >>= 1) v += __shfl_down_sync(0xFFFFFFFFu, v, o);
        if (lane == 0) g_bsum[blockIdx.x] = v;
    }
}

__global__ void scan_bsums(int B) {           // single block, 1024 threads
    __shared__ unsigned sh[1024];
    int tid = threadIdx.x;
    unsigned v = (tid < B) ? g_bsum[tid] : 0u;
    sh[tid] = v;
    __syncthreads();
    for (int off = 1; off < 1024; off <<= 1) {
        unsigned t = (tid >= off) ? sh[tid - off] : 0u;
        __syncthreads();
        sh[tid] += t;
        __syncthreads();
    }
    if (tid < B) g_boff[tid] = sh[tid] - v;   // exclusive
}

__global__ void emit_rowptr(int N) {
    int b = blockIdx.x, tid = threadIdx.x;
    int lane = tid & 31, wid = tid >> 5;
    int i = b * 1024 + tid;
    unsigned v = (i < N) ? g_deg[i] : 0u;
    unsigned x = v;
    #pragma unroll
    for (int o = 1; o < 32; o <<= 1) {
        unsigned t = __shfl_up_sync(0xFFFFFFFFu, x, o);
        if (lane >= o) x += t;
    }
    __shared__ unsigned wsum[32];
    if (lane == 31) wsum[wid] = x;
    __syncthreads();
    if (wid == 0) {
        unsigned w = wsum[lane], orig = w;
        #pragma unroll
        for (int o = 1; o < 32; o <<= 1) {
            unsigned t = __shfl_up_sync(0xFFFFFFFFu, w, o);
            if (lane >= o) w += t;
        }
        wsum[lane] = w - orig;
    }
    __syncthreads();
    unsigned ex = (x - v) + wsum[wid] + g_boff[b];
    if (i < N) {
        g_rowptr[i] = (int)ex;
        g_cursor[i] = (int)ex;
        if (i == N - 1) g_rowptr[N] = (int)(ex + v);
    }
}

// ---------------------------------------------------------------------------
// fill CSR columns only (weights folded into prescaled rows).
// ---------------------------------------------------------------------------
__global__ void fill_kernel(const int* __restrict__ src,
                            const int* __restrict__ dst, int E) {
    int e = blockIdx.x * blockDim.x + threadIdx.x;
    if (e >= E) return;
    int s = __ldg(src + e);
    int d = __ldg(dst + e);
    int pos = atomicAdd(&g_cursor[d], 1);
    g_col[pos] = s;
}

// ---------------------------------------------------------------------------
// prescale: g_xA[n] = dinv[n] * concat(Gu, Gi)[n]   (float4 granularity)
// ---------------------------------------------------------------------------
__global__ void prescale_kernel(const float* __restrict__ Gu,
                                const float* __restrict__ Gi,
                                int U, int N) {
    long long i = (long long)blockIdx.x * blockDim.x + threadIdx.x;
    long long total4 = (long long)N * (D / 4);
    if (i >= total4) return;
    int node = (int)(i >> 4);
    long long ub4 = (long long)U * (D / 4);
    float4 v = (i < ub4) ? ((const float4*)Gu)[i]
                         : ((const float4*)Gi)[i - ub4];
    float di = __ldg(g_dinv + node);
    v.x *= di; v.y *= di; v.z *= di; v.w *= di;
    ((float4*)g_xA)[i] = v;
}

// ---------------------------------------------------------------------------
// Fused gather (unweighted sum of prescaled rows) + dinv_d scale + noise
// perturbation + accumulation. Warp per node; lane holds float2.
//   LAYER 0: read g_xA, write g_xB(prescaled), acc  = s/3
//   LAYER 1: read g_xB, write g_xA(prescaled), acc += s/3
//   LAYER 2: read g_xA, no x write,            acc += s/3, re-zero g_deg
// ---------------------------------------------------------------------------
__device__ __forceinline__ float sgnf(float v) {
    return (v > 0.f) ? 1.f : ((v < 0.f) ? -1.f : 0.f);
}

template <int LAYER>
__global__ void gather_perturb(const float* __restrict__ noise,
                               float* __restrict__ acc, int N) {
    long long t = (long long)blockIdx.x * blockDim.x + threadIdx.x;
    int n = (int)(t >> 5);
    if (n >= N) return;
    int lane = threadIdx.x & 31;

    const float* x = (LAYER == 1) ? g_xB : g_xA;

    int beg = __ldg(g_rowptr + n);
    int end = __ldg(g_rowptr + n + 1);

    // hoist independent loads
    float2 nv = __ldg((const float2*)(noise + (long long)n * D) + lane);
    float  di = __ldg(g_dinv + n);

    float2 s = make_float2(0.f, 0.f);
    for (int j0 = beg; j0 < end; j0 += 32) {
        int jj = j0 + lane;
        int col = (jj < end) ? __ldg(g_col + jj) : 0;
        int cnt = min(32, end - j0);     // warp-uniform
        int k = 0;
        for (; k + 4 <= cnt; k += 4) {
            int c0 = __shfl_sync(0xFFFFFFFFu, col, k);
            int c1 = __shfl_sync(0xFFFFFFFFu, col, k + 1);
            int c2 = __shfl_sync(0xFFFFFFFFu, col, k + 2);
            int c3 = __shfl_sync(0xFFFFFFFFu, col, k + 3);
            float2 v0 = __ldg((const float2*)(x + (long long)c0 * D) + lane);
            float2 v1 = __ldg((const float2*)(x + (long long)c1 * D) + lane);
            float2 v2 = __ldg((const float2*)(x + (long long)c2 * D) + lane);
            float2 v3 = __ldg((const float2*)(x + (long long)c3 * D) + lane);
            s.x += v0.x; s.y += v0.y;
            s.x += v1.x; s.y += v1.y;
            s.x += v2.x; s.y += v2.y;
            s.x += v3.x; s.y += v3.y;
        }
        for (; k < cnt; k++) {
            int c = __shfl_sync(0xFFFFFFFFu, col, k);
            float2 v = __ldg((const float2*)(x + (long long)c * D) + lane);
            s.x += v.x; s.y += v.y;
        }
    }

    s.x *= di; s.y *= di;

    // perturb: s += sign(s) * (noise_row / max(||noise_row||,1e-12)) * EPS
    float ss = nv.x * nv.x + nv.y * nv.y;
    #pragma unroll
    for (int o = 16; o; o >>= 1) ss += __shfl_xor_sync(0xFFFFFFFFu, ss, o);
    float scale = EPSV / fmaxf(sqrtf(ss), 1e-12f);
    s.x += sgnf(s.x) * nv.x * scale;
    s.y += sgnf(s.y) * nv.y * scale;

    if (LAYER != 2) {   // store prescaled for next layer
        float* xn = (LAYER == 0) ? g_xB : g_xA;
        ((float2*)(xn + (long long)n * D))[lane] =
            make_float2(s.x * di, s.y * di);
    }

    const float third = 1.f / 3.f;
    float2* ap = (float2*)(acc + (long long)n * D) + lane;
    if (LAYER == 0) {
        *ap = make_float2(s.x * third, s.y * third);
    } else {
        float2 av = *ap;
        av.x += s.x * third;
        av.y += s.y * third;
        *ap = av;
    }

    if (LAYER == 2 && lane == 0) g_deg[n] = 0u;   // restore invariant
}

// ---------------------------------------------------------------------------
extern "C" void kernel_launch(void* const* d_in, const int* in_sizes, int n_in,
                              void* d_out, int out_size) {
    const float* Gu = (const float*)d_in[0];
    const float* Gi = (const float*)d_in[1];
    const float* nz = (const float*)d_in[2];
    const int*   ei = (const int*)d_in[3];

    int U = in_sizes[0] / D;
    int I = in_sizes[1] / D;
    int N = U + I;
    int E = in_sizes[3] / 2;

    const int* src = ei;
    const int* dst = ei + E;
    float* acc = (float*)d_out;

    const int TPB = 256;
    int blks_E = (E + TPB - 1) / TPB;
    int blks_N = (N + TPB - 1) / TPB;
    int B      = (N + 1023) / 1024;
    long long total4 = (long long)N * (D / 4);
    int blks_p = (int)((total4 + TPB - 1) / TPB);
    long long node_threads = (long long)N * 32;
    int blks_g = (int)((node_threads + TPB - 1) / TPB);

    long long nd = (long long)N * D;

    deg_kernel<<<blks_E, TPB>>>(dst, E);
    dinv_kernel<<<blks_N, TPB>>>(N);
    tile_reduce<<<B, 1024>>>(N);
    scan_bsums<<<1, 1024>>>(B);
    emit_rowptr<<<B, 1024>>>(N);
    fill_kernel<<<blks_E, TPB>>>(src, dst, E);
    prescale_kernel<<<blks_p, TPB>>>(Gu, Gi, U, N);
    gather_perturb<0><<<blks_g, TPB>>>(nz,          acc, N);
    gather_perturb<1><<<blks_g, TPB>>>(nz + nd,     acc, N);
    gather_perturb<2><<<blks_g, TPB>>>(nz + 2 * nd, acc, N);
}